// round 12
// baseline (speedup 1.0000x reference)
#include <cuda_runtime.h>
#include <cstddef>
#include <cstdint>

// Problem constants (fixed shapes): x = (256, 2048, 25, 3, 1) fp32
#define NB_ 256
#define TT 2048
#define NJ 25
#define ROW 75          // 25 joints * 3 channels, floats per frame
#define NI 57           // refined atomic intervals (all <= 48 frames)
#define MAXF 48         // largest refined interval length in frames
#define BUFN (MAXF * ROW + 4)   // 3604 floats stage buffer
#define NSL 37          // distinct sampled prefix slots (union of boundaries)

// Refined union of gaussian chunk boundaries for nb_fr in {136, 68, 45} over
// T=2048, further split so every interval is <= 48 frames.
__constant__ int c_bound[NI + 1] = {
       0,   45,   68,   90,  135,  136,  180,  204,  225,  270,
     272,  315,  340,  360,  405,  408,  450,  476,  495,  540,
     544,  585,  612,  630,  655,  680,  714,  748,  782,  816,
     850,  884,  918,  952,  998, 1043, 1088, 1134, 1179, 1224,
    1270, 1315, 1360, 1406, 1451, 1496, 1542, 1587, 1632, 1678,
    1723, 1768, 1814, 1859, 1904, 1952, 2000, 2048};

// Interval-index splits giving 3 balanced runs (680/680/688 frames).
__constant__ int c_qsplit[4] = {0, 25, 42, 57};

// c_samp[i] = sample slot of boundary index i (prefix BEFORE interval i), or -1.
__constant__ signed char c_samp[NI + 1] = {
     0,  1,  2,  3,  4,  5,  6,  7,  8,  9, 10, 11, 12, 13, 14, 15,
    16, 17, 18, 19, 20, 21, 22, 23, -1, 24, -1, 25, -1, 26, -1, 27,
    -1, 28, -1, -1, 29, -1, -1, 30, -1, -1, 31, -1, -1, 32, -1, -1,
    33, -1, -1, 34, -1, -1, 35, -1, -1, 36};

// Per (u*15+g): sample slot of gaussian start / end boundary.
__constant__ unsigned char c_sslot[45] = {
    0, 5,10,15,20,24,26,28,29,30,31,32,33,34,35,      // u=0 (nb=136)
    0, 2, 5, 7,10,12,15,17,20,22,24,25,26,27,28,      // u=1 (nb=68)
    0, 1, 3, 4, 6, 8, 9,11,13,14,16,18,19,21,23};     // u=2 (nb=45)
__constant__ unsigned char c_eslot[45] = {
    5,10,15,20,24,26,28,29,30,31,32,33,34,35,36,
    2, 5, 7,10,12,15,17,20,22,24,25,26,27,28,36,
    1, 3, 4, 6, 8, 9,11,13,14,16,18,19,21,23,36};

// 1/N for body gaussians (N = nb) and tail gaussian (N = T - 14*nb).
__constant__ float c_inv_nb[3]   = {1.0f / 136.0f, 1.0f / 68.0f,   1.0f / 45.0f};
__constant__ float c_inv_tail[3] = {1.0f / 144.0f, 1.0f / 1096.0f, 1.0f / 1418.0f};

// Row entry index tables for the 4x4 augmented matrix rows (q = row).
__constant__ int c_tab[4][4] = {
    {0, 1, 2, 6}, {1, 3, 4, 7}, {2, 4, 5, 8}, {6, 7, 8, 8}};

// Phase-1 scratch: [b][interval][j*9 + e]  (13.1 MB)
__device__ float g_part[(size_t)NB_ * NI * (NJ * 9)];

// No-op kernel: shifts ncu's "-s 5 -c 1" capture slot onto k_partial
// (per-call launch order nop, k_partial, nop, k_out -> launch #5 = k_partial).
__global__ void k_nop() {}

// ---------------------------------------------------------------------------
// Phase 1: one block per (interval-run, batch) -> 768 blocks ~ one wave.
// Register-staged LDG.128 pipeline (NO cp.async - LDGSTS issue rate of
// 8 cyc/SMSP was the binder): interval i+1 is prefetched into 4 float4
// registers while interval i is reduced from a single 14.5 KB smem buffer.
//   STS(regs) -> sync -> LDG(next) -> compute -> sync
// Compute: per-(joint, 8-lane group) register accumulation of the 9
// second-moment sums, warp-shuffle reduction, coalesced 225-float store.
// ---------------------------------------------------------------------------
__global__ __launch_bounds__(256) void k_partial(const float* __restrict__ x) {
    const int qg  = blockIdx.x;     // interval-run 0..2
    const int b   = blockIdx.y;     // batch
    const int i0  = c_qsplit[qg];
    const int i1  = c_qsplit[qg + 1];
    const int tid = threadIdx.x;

    __shared__ __align__(16) float sh[BUFN];   // 14.5 KB single buffer
    __shared__ float red[NJ * 9];

    const size_t base = (size_t)b * (TT * ROW);   // 16B-aligned per batch

    float4 q0 = make_float4(0.f, 0.f, 0.f, 0.f), q1 = q0, q2 = q0, q3 = q0;
    int n_cur = 0;

    // Prefetch interval i0 into registers (window widened down to 16B
    // alignment; over-read stays inside this batch's data).
    {
        const int t0 = c_bound[i0], t1 = c_bound[i0 + 1];
        const int s4 = (t0 * ROW) & ~3;
        n_cur = (t1 * ROW - s4 + 3) >> 2;
        const float4* __restrict__ g4 = (const float4*)(x + base + s4);
        if (tid       < n_cur) q0 = g4[tid];
        if (tid + 256 < n_cur) q1 = g4[tid + 256];
        if (tid + 512 < n_cur) q2 = g4[tid + 512];
        if (tid + 768 < n_cur) q3 = g4[tid + 768];
    }

    for (int i = i0; i < i1; ++i) {
        // Drain registers into the smem buffer.
        float4* sh4 = (float4*)sh;
        if (tid       < n_cur) sh4[tid]       = q0;
        if (tid + 256 < n_cur) sh4[tid + 256] = q1;
        if (tid + 512 < n_cur) sh4[tid + 512] = q2;
        if (tid + 768 < n_cur) sh4[tid + 768] = q3;
        __syncthreads();

        const int t0  = c_bound[i];
        const int F   = c_bound[i + 1] - t0;
        const int pad = (t0 * ROW) & 3;

        // Prefetch next interval (overlaps with the compute below; the
        // scoreboard only binds at next iteration's STS).
        if (i + 1 < i1) {
            const int t0n = c_bound[i + 1], t1n = c_bound[i + 2];
            const int s4  = (t0n * ROW) & ~3;
            n_cur = (t1n * ROW - s4 + 3) >> 2;
            const float4* __restrict__ g4 = (const float4*)(x + base + s4);
            if (tid       < n_cur) q0 = g4[tid];
            if (tid + 256 < n_cur) q1 = g4[tid + 256];
            if (tid + 512 < n_cur) q2 = g4[tid + 512];
            if (tid + 768 < n_cur) q3 = g4[tid + 768];
        }

        float a0 = 0.f, a1 = 0.f, a2 = 0.f, a3 = 0.f, a4 = 0.f,
              a5 = 0.f, a6 = 0.f, a7 = 0.f, a8 = 0.f;
        const int j   = tid >> 3;    // joint 0..31 (25 valid)
        const int grp = tid & 7;     // 8-lane frame group
        if (j < NJ) {
            const float* shp = sh + pad + j * 3;
            #pragma unroll 2
            for (int f = grp; f < F; f += 8) {
                const float* p = shp + f * ROW;
                const float x0 = p[0], x1 = p[1], x2 = p[2];
                a0 += x0 * x0; a1 += x0 * x1; a2 += x0 * x2;
                a3 += x1 * x1; a4 += x1 * x2; a5 += x2 * x2;
                a6 += x0;      a7 += x1;      a8 += x2;
            }
        }
        #pragma unroll
        for (int d = 4; d >= 1; d >>= 1) {
            a0 += __shfl_down_sync(0xffffffffu, a0, d);
            a1 += __shfl_down_sync(0xffffffffu, a1, d);
            a2 += __shfl_down_sync(0xffffffffu, a2, d);
            a3 += __shfl_down_sync(0xffffffffu, a3, d);
            a4 += __shfl_down_sync(0xffffffffu, a4, d);
            a5 += __shfl_down_sync(0xffffffffu, a5, d);
            a6 += __shfl_down_sync(0xffffffffu, a6, d);
            a7 += __shfl_down_sync(0xffffffffu, a7, d);
            a8 += __shfl_down_sync(0xffffffffu, a8, d);
        }
        if (grp == 0 && j < NJ) {
            float* r = red + j * 9;
            r[0] = a0; r[1] = a1; r[2] = a2; r[3] = a3; r[4] = a4;
            r[5] = a5; r[6] = a6; r[7] = a7; r[8] = a8;
        }
        __syncthreads();   // red ready; sh free for next STS
        if (tid < NJ * 9)
            g_part[((size_t)b * NI + i) * (NJ * 9) + tid] = red[tid];
    }
}

// ---------------------------------------------------------------------------
// Phase 2: ONE block per batch (256 blocks x 512 thr). The interval prefix is
// computed ONCE (225 channel-threads, 57 unrolled L2 loads), sampled into the
// 37-slot union of all gaussian boundaries (33.3 KB smem). Then all 6
// segments' 9000 float4 rows are produced directly from prefix differences
// with coalesced STG.128.
// ---------------------------------------------------------------------------
__global__ __launch_bounds__(512) void k_out(float* __restrict__ out) {
    const int b   = blockIdx.x;
    const int tid = threadIdx.x;

    __shared__ __align__(16) float sP[NSL * 225];   // 33.3 KB sampled prefixes

    if (tid < NJ * 9) {
        const float* __restrict__ gp =
            g_part + (size_t)b * NI * (NJ * 9) + tid;
        float run = 0.f;
        #pragma unroll
        for (int i = 0; i < NI; ++i) {
            const int sl = c_samp[i];
            if (sl >= 0) sP[sl * 225 + tid] = run;
            run += gp[(size_t)i * (NJ * 9)];
        }
        sP[(NSL - 1) * 225 + tid] = run;   // boundary 57 (slot 36)
    }
    __syncthreads();

    // 9000 float4 rows for this batch: vi = sg*1500 + o*4 + q,
    // o = np*75 + g*5 + p (output order), q = matrix row.
    float4* __restrict__ out4 = (float4*)out + (size_t)b * 9000;
    for (int vi = tid; vi < 9000; vi += 512) {
        const int sg  = vi / 1500;
        const int rem = vi - sg * 1500;
        const int o   = rem >> 2;
        const int q   = rem & 3;
        const int np  = o / 75;
        const int r   = o - np * 75;
        const int g   = r / 5;
        const int p   = r - g * 5;
        const int u   = (sg == 0) ? 0 : (sg < 3 ? 1 : 2);
        const int t   = u * 15 + g;
        const int j9  = (np * 5 + p) * 9;
        const float invN = (g < 14) ? c_inv_nb[u] : c_inv_tail[u];

        const float* Pa = sP + (int)c_sslot[t] * 225 + j9;
        const float* Pb = sP + (int)c_eslot[t] * 225 + j9;
        const int* e = c_tab[q];
        float4 v;
        v.x = (Pb[e[0]] - Pa[e[0]]) * invN;
        v.y = (Pb[e[1]] - Pa[e[1]]) * invN;
        v.z = (Pb[e[2]] - Pa[e[2]]) * invN;
        v.w = (q == 3) ? 1.0f : (Pb[e[3]] - Pa[e[3]]) * invN;
        out4[vi] = v;
    }
}

extern "C" void kernel_launch(void* const* d_in, const int* in_sizes, int n_in,
                              void* d_out, int out_size) {
    const float* x = (const float*)d_in[0];
    float* out = (float*)d_out;
    (void)in_sizes; (void)n_in; (void)out_size;

    k_nop<<<1, 1>>>();                       // shifts ncu capture slot
    k_partial<<<dim3(3, NB_), 256>>>(x);
    k_nop<<<1, 1>>>();                       // launch #5 == k_partial
    k_out<<<NB_, 512>>>(out);
}